// round 1
// baseline (speedup 1.0000x reference)
#include <cuda_runtime.h>
#include <cuda_bf16.h>
#include <cstdint>

#define Bb   128
#define Tt   512
#define Ee   100
#define Uu   128
#define Kk   32
#define G4   512          // 4*U
#define BT   (Bb*Tt)      // 65536

// ---------------- scratch (static device allocations) ----------------
__device__ float g_zx[(size_t)2 * BT * G4];   // [dir][b*T+t][512]  (x@Wk + bias)
__device__ float g_h [(size_t)2 * BT * Uu];   // [dir][b*T+t][128]
__device__ float g_em[(size_t)BT * Kk];       // [b*T+t][32]

// ---------------- fast math helpers ----------------
__device__ __forceinline__ float ex2f(float x){ float r; asm("ex2.approx.f32 %0, %1;" : "=f"(r) : "f"(x)); return r; }
__device__ __forceinline__ float lg2f(float x){ float r; asm("lg2.approx.f32 %0, %1;" : "=f"(r) : "f"(x)); return r; }
__device__ __forceinline__ float tanhfast(float x){ float r; asm("tanh.approx.f32 %0, %1;" : "=f"(r) : "f"(x)); return r; }
__device__ __forceinline__ float sigfast(float x){ return 0.5f * tanhfast(0.5f * x) + 0.5f; }
__device__ __forceinline__ float blo(unsigned u){ return __uint_as_float(u << 16); }
__device__ __forceinline__ float bhi(unsigned u){ return __uint_as_float(u & 0xffff0000u); }

// =====================================================================
// Kernel A: zx[dir][bt][j] = emb[tokens[bt]] @ Wk_dir + b_dir
// grid (BT/64, 16), block 256.  Each block: 64 bt-rows x 64 cols.
// =====================================================================
__global__ void input_gemm(const int* __restrict__ tokens,
                           const float* __restrict__ emb,
                           const float* __restrict__ Wk_f, const float* __restrict__ b_f,
                           const float* __restrict__ Wk_b, const float* __restrict__ b_b)
{
    __shared__ float xs[64][Ee];        // 64 x 100
    __shared__ float ws[Ee][64];        // 100 x 64  (row = 256B, float4-friendly)
    __shared__ int   tok_s[64];
    __shared__ float bs[64];

    const int tid = threadIdx.x;
    const int r0  = blockIdx.x * 64;
    const int c0  = blockIdx.y * 64;
    const int dir = c0 >> 9;            // constant per block (cols 0..511 fw, 512..1023 bw)

    if (tid < 64) {
        tok_s[tid] = tokens[r0 + tid];
        int cg = c0 + tid;
        bs[tid] = (cg < 512) ? b_f[cg] : b_b[cg - 512];
    }
    __syncthreads();

    // load x tile (gathered embeddings)
    for (int idx = tid; idx < 64 * Ee; idx += 256) {
        int r = idx / Ee, k = idx % Ee;
        xs[r][k] = emb[(size_t)tok_s[r] * Ee + k];
    }
    // load W tile
    for (int idx = tid; idx < Ee * 64; idx += 256) {
        int k = idx >> 6, c = idx & 63;
        int cg = c0 + c;
        ws[k][c] = (cg < 512) ? Wk_f[k * G4 + cg] : Wk_b[k * G4 + (cg - 512)];
    }
    __syncthreads();

    const int ty = tid >> 4, tx = tid & 15;
    float acc[4][4];
#pragma unroll
    for (int i = 0; i < 4; i++)
#pragma unroll
        for (int j = 0; j < 4; j++) acc[i][j] = 0.f;

#pragma unroll 4
    for (int k = 0; k < Ee; k++) {
        float4 wv = *(const float4*)&ws[k][4 * tx];
#pragma unroll
        for (int i = 0; i < 4; i++) {
            float xv = xs[4 * ty + i][k];
            acc[i][0] += xv * wv.x; acc[i][1] += xv * wv.y;
            acc[i][2] += xv * wv.z; acc[i][3] += xv * wv.w;
        }
    }

#pragma unroll
    for (int i = 0; i < 4; i++) {
        int rg = r0 + 4 * ty + i;
#pragma unroll
        for (int j = 0; j < 4; j++) {
            int c  = 4 * tx + j;
            int jj = (c0 + c) - dir * 512;
            g_zx[((size_t)dir * BT + rg) * G4 + jj] = acc[i][j] + bs[c];
        }
    }
}

// =====================================================================
// Kernel B: LSTM recurrence. 128 blocks x 512 threads.
// block = (dir, batch pair). Wr as bf16 in smem, padded column-major.
// =====================================================================
#define WR_PAD 136
#define SMEM_B (G4*WR_PAD*2 + 2*G4*4 + 2*Uu*4)   // 139264 + 4096 + 1024

__global__ void __launch_bounds__(512, 1)
lstm_rec(const float* __restrict__ Wr_f, const float* __restrict__ Wr_b)
{
    extern __shared__ char smem[];
    __nv_bfloat16* wr_s = (__nv_bfloat16*)smem;                 // [j*136 + k]
    float* z_s = (float*)(smem + G4 * WR_PAD * 2);              // [2][512]
    float* h_s = z_s + 2 * G4;                                  // [2][128]

    const int tid  = threadIdx.x;
    const int bx   = blockIdx.x;
    const int dir  = bx >> 6;
    const int pair = bx & 63;
    const int b0   = 2 * pair;
    const float* Wr = dir ? Wr_b : Wr_f;

    // stage weights: wr_s[j*136 + k] = bf16(Wr[k][j])
    for (int idx = tid; idx < Uu * G4; idx += 512) {
        int k = idx >> 9, j = idx & 511;
        wr_s[j * WR_PAD + k] = __float2bfloat16(Wr[k * G4 + j]);
    }
    if (tid < 256) h_s[tid & 255] = 0.f;   // h_s[2][128] zero
    float c_reg = 0.f;
    __syncthreads();

    const int j = tid;
    const uint4*  wp  = (const uint4*)(wr_s + j * WR_PAD);
    const float4* h0p = (const float4*)h_s;
    const float4* h1p = (const float4*)(h_s + Uu);
    const float* zx0 = g_zx + ((size_t)dir * BT + (size_t)(b0 + 0) * Tt) * G4;
    const float* zx1 = g_zx + ((size_t)dir * BT + (size_t)(b0 + 1) * Tt) * G4;
    float* hout = g_h + (size_t)dir * BT * Uu;

    for (int step = 0; step < Tt; step++) {
        const int t = dir ? (Tt - 1 - step) : step;

        float a0a = zx0[(size_t)t * G4 + j], a0b = 0.f;
        float a1a = zx1[(size_t)t * G4 + j], a1b = 0.f;

#pragma unroll
        for (int kk = 0; kk < 16; kk++) {
            uint4  wv  = wp[kk];
            float4 h0a = h0p[2 * kk], h0b = h0p[2 * kk + 1];
            float4 h1a = h1p[2 * kk], h1b = h1p[2 * kk + 1];
            float w0 = blo(wv.x), w1 = bhi(wv.x), w2 = blo(wv.y), w3 = bhi(wv.y);
            float w4 = blo(wv.z), w5 = bhi(wv.z), w6 = blo(wv.w), w7 = bhi(wv.w);
            a0a += w0*h0a.x; a0a += w1*h0a.y; a0a += w2*h0a.z; a0a += w3*h0a.w;
            a0b += w4*h0b.x; a0b += w5*h0b.y; a0b += w6*h0b.z; a0b += w7*h0b.w;
            a1a += w0*h1a.x; a1a += w1*h1a.y; a1a += w2*h1a.z; a1a += w3*h1a.w;
            a1b += w4*h1b.x; a1b += w5*h1b.y; a1b += w6*h1b.z; a1b += w7*h1b.w;
        }
        z_s[j]      = a0a + a0b;
        z_s[G4 + j] = a1a + a1b;
        __syncthreads();

        if (tid < 256) {
            int bsel = tid >> 7, jj = tid & 127;
            const float* z = z_s + bsel * G4;
            float zi = z[jj], zf = z[jj + 128], zg = z[jj + 256], zo = z[jj + 384];
            c_reg = sigfast(zf) * c_reg + sigfast(zi) * tanhfast(zg);
            float h = sigfast(zo) * tanhfast(c_reg);
            h_s[bsel * Uu + jj] = h;
            hout[((size_t)(b0 + bsel) * Tt + t) * Uu + jj] = h;
        }
        __syncthreads();
    }
}

// =====================================================================
// Kernel C: em = [h_f, h_b] @ crf_kernel + bias.  grid BT/8, block 256.
// =====================================================================
__global__ void em_gemm(const float* __restrict__ ck, const float* __restrict__ cb)
{
    __shared__ float ck_s[2 * Uu][Kk];      // 256 x 32 = 32KB
    __shared__ float hs[8][2 * Uu];         // 8 rows x 256
    __shared__ float cb_s[Kk];

    const int tid = threadIdx.x;
    const int bt0 = blockIdx.x * 8;

    for (int idx = tid; idx < 2 * Uu * Kk; idx += 256)
        ck_s[idx >> 5][idx & 31] = ck[idx];
    if (tid < Kk) cb_s[tid] = cb[tid];
    for (int idx = tid; idx < 8 * 2 * Uu; idx += 256) {
        int r = idx >> 8, u = idx & 255;
        hs[r][u] = (u < Uu) ? g_h[(size_t)(bt0 + r) * Uu + u]
                            : g_h[(size_t)BT * Uu + (size_t)(bt0 + r) * Uu + (u - Uu)];
    }
    __syncthreads();

    const int r = tid >> 5, k = tid & 31;
    float acc = cb_s[k];
#pragma unroll 8
    for (int u = 0; u < 2 * Uu; u++)
        acc += hs[r][u] * ck_s[u][k];
    g_em[(size_t)(bt0 + r) * Kk + k] = acc;
}

// =====================================================================
// Kernel D: CRF logZ. 128 blocks x 32 threads (one warp per batch).
// alpha_new[k] = log( sum_j exp(alpha_j - m) * exp(trans[j][k]) ) + m + em[t][k]
// =====================================================================
__global__ void crf_logz(const float* __restrict__ trans, float* __restrict__ out)
{
    const float L2E = 1.4426950408889634f, LN2 = 0.6931471805599453f;
    const int b = blockIdx.x;
    const int k = threadIdx.x;           // lane
    const unsigned full = 0xffffffffu;

    float Ecol[Kk];
#pragma unroll
    for (int jj = 0; jj < Kk; jj++)
        Ecol[jj] = ex2f(trans[jj * Kk + k] * L2E);

    const float* em = g_em + (size_t)b * Tt * Kk;
    float alpha = em[k];                 // t = 0

    for (int t = 1; t < Tt; t++) {
        float m = alpha;
#pragma unroll
        for (int o = 16; o; o >>= 1) m = fmaxf(m, __shfl_xor_sync(full, m, o));
        float e = ex2f((alpha - m) * L2E);
        float s = 0.f;
#pragma unroll
        for (int jj = 0; jj < Kk; jj++)
            s += __shfl_sync(full, e, jj) * Ecol[jj];
        alpha = lg2f(s) * LN2 + m + em[(size_t)t * Kk + k];
    }

    float m = alpha;
#pragma unroll
    for (int o = 16; o; o >>= 1) m = fmaxf(m, __shfl_xor_sync(full, m, o));
    float s = ex2f((alpha - m) * L2E);
#pragma unroll
    for (int o = 16; o; o >>= 1) s += __shfl_xor_sync(full, s, o);
    if (k == 0) out[b] = m + lg2f(s) * LN2;
}

// =====================================================================
extern "C" void kernel_launch(void* const* d_in, const int* in_sizes, int n_in,
                              void* d_out, int out_size)
{
    const int*   tokens = (const int*)  d_in[0];
    const float* emb    = (const float*)d_in[1];
    const float* Wk_f   = (const float*)d_in[2];
    const float* Wr_f   = (const float*)d_in[3];
    const float* b_f    = (const float*)d_in[4];
    const float* Wk_b   = (const float*)d_in[5];
    const float* Wr_b   = (const float*)d_in[6];
    const float* b_b    = (const float*)d_in[7];
    const float* ck     = (const float*)d_in[8];
    const float* cb     = (const float*)d_in[9];
    const float* trans  = (const float*)d_in[10];
    float* out = (float*)d_out;

    cudaFuncSetAttribute(lstm_rec, cudaFuncAttributeMaxDynamicSharedMemorySize, SMEM_B);

    input_gemm<<<dim3(BT / 64, 16), 256>>>(tokens, emb, Wk_f, b_f, Wk_b, b_b);
    lstm_rec<<<128, 512, SMEM_B>>>(Wr_f, Wr_b);
    em_gemm<<<BT / 8, 256>>>(ck, cb);
    crf_logz<<<Bb, 32>>>(trans, out);
}

// round 2
// speedup vs baseline: 1.1896x; 1.1896x over previous
#include <cuda_runtime.h>
#include <cuda_bf16.h>
#include <cstdint>

typedef unsigned long long ull;

#define Bb   128
#define Tt   512
#define Ee   100
#define Uu   128
#define Kk   32
#define G4   512          // 4*U
#define BT   (Bb*Tt)      // 65536

// ---------------- scratch (static device allocations) ----------------
__device__ float g_zx[(size_t)2 * BT * G4];   // [dir][b*T+t][512]  (x@Wk + bias)
__device__ float g_h [(size_t)2 * BT * Uu];   // [dir][b*T+t][128]
__device__ float g_em[(size_t)BT * Kk];       // [b*T+t][32]

// ---------------- fast math helpers ----------------
__device__ __forceinline__ float ex2f(float x){ float r; asm("ex2.approx.f32 %0, %1;" : "=f"(r) : "f"(x)); return r; }
__device__ __forceinline__ float lg2f(float x){ float r; asm("lg2.approx.f32 %0, %1;" : "=f"(r) : "f"(x)); return r; }
__device__ __forceinline__ float tanhfast(float x){ float r; asm("tanh.approx.f32 %0, %1;" : "=f"(r) : "f"(x)); return r; }
__device__ __forceinline__ float sigfast(float x){ return 0.5f * tanhfast(0.5f * x) + 0.5f; }

// ---------------- f32x2 (FFMA2) helpers ----------------
// bf16x2 word (k even in low 16, k+1 in high 16) -> f32x2 pair (f(k), f(k+1))
__device__ __forceinline__ ull bfpair(unsigned u){
    unsigned lo = u << 16;
    unsigned hi = u & 0xffff0000u;
    ull r; asm("mov.b64 %0, {%1, %2};" : "=l"(r) : "r"(lo), "r"(hi)); return r;
}
__device__ __forceinline__ ull dup2(float x){
    ull r; asm("mov.b64 %0, {%1, %1};" : "=l"(r) : "f"(x)); return r;
}
__device__ __forceinline__ ull fma2(ull a, ull b, ull c){
    ull d; asm("fma.rn.f32x2 %0, %1, %2, %3;" : "=l"(d) : "l"(a), "l"(b), "l"(c)); return d;
}
__device__ __forceinline__ void unpk2(ull v, float& lo, float& hi){
    asm("mov.b64 {%0, %1}, %2;" : "=f"(lo), "=f"(hi) : "l"(v));
}
// 16B shared load as two f32x2 (4 consecutive floats)
__device__ __forceinline__ void ldsv2(ull& a, ull& b, const void* p){
    unsigned s = (unsigned)__cvta_generic_to_shared(p);
    asm volatile("ld.shared.v2.u64 {%0, %1}, [%2];" : "=l"(a), "=l"(b) : "r"(s));
}

// =====================================================================
// Kernel A: zx[dir][bt][j] = emb[tokens[bt]] @ Wk_dir + b_dir
// grid (BT/64, 16), block 256.  Each block: 64 bt-rows x 64 cols.
// Inner product uses fma.rn.f32x2 (2 MACs/instr).
// =====================================================================
__global__ void input_gemm(const int* __restrict__ tokens,
                           const float* __restrict__ emb,
                           const float* __restrict__ Wk_f, const float* __restrict__ b_f,
                           const float* __restrict__ Wk_b, const float* __restrict__ b_b)
{
    __shared__ float xs[64][Ee];        // 64 x 100
    __shared__ float ws[Ee][64];        // 100 x 64
    __shared__ int   tok_s[64];
    __shared__ float bs[64];

    const int tid = threadIdx.x;
    const int r0  = blockIdx.x * 64;
    const int c0  = blockIdx.y * 64;
    const int dir = c0 >> 9;

    if (tid < 64) {
        tok_s[tid] = tokens[r0 + tid];
        int cg = c0 + tid;
        bs[tid] = (cg < 512) ? b_f[cg] : b_b[cg - 512];
    }
    __syncthreads();

    for (int idx = tid; idx < 64 * Ee; idx += 256) {
        int r = idx / Ee, k = idx % Ee;
        xs[r][k] = emb[(size_t)tok_s[r] * Ee + k];
    }
    for (int idx = tid; idx < Ee * 64; idx += 256) {
        int k = idx >> 6, c = idx & 63;
        int cg = c0 + c;
        ws[k][c] = (cg < 512) ? Wk_f[k * G4 + cg] : Wk_b[k * G4 + (cg - 512)];
    }
    __syncthreads();

    const int ty = tid >> 4, tx = tid & 15;
    ull acc[4][2];
#pragma unroll
    for (int i = 0; i < 4; i++) { acc[i][0] = 0ull; acc[i][1] = 0ull; }

#pragma unroll 4
    for (int k = 0; k < Ee; k++) {
        ull w01, w23;
        ldsv2(w01, w23, &ws[k][4 * tx]);
#pragma unroll
        for (int i = 0; i < 4; i++) {
            ull xd = dup2(xs[4 * ty + i][k]);
            acc[i][0] = fma2(xd, w01, acc[i][0]);
            acc[i][1] = fma2(xd, w23, acc[i][1]);
        }
    }

#pragma unroll
    for (int i = 0; i < 4; i++) {
        int rg = r0 + 4 * ty + i;
        float v0, v1, v2, v3;
        unpk2(acc[i][0], v0, v1);
        unpk2(acc[i][1], v2, v3);
        int c = 4 * tx;
        int jj = (c0 + c) - dir * 512;
        float* dst = g_zx + ((size_t)dir * BT + rg) * G4 + jj;
        dst[0] = v0 + bs[c + 0];
        dst[1] = v1 + bs[c + 1];
        dst[2] = v2 + bs[c + 2];
        dst[3] = v3 + bs[c + 3];
    }
}

// =====================================================================
// Kernel B: LSTM recurrence. 128 blocks x 512 threads.
// Weights bf16 in smem (68 uint32 words / column, stride 68 == 4 mod 32
// -> conflict-free LDS.128). Inner dot uses fma.rn.f32x2 over k-pairs;
// h pairs come directly from ld.shared.v2.u64 (no pack instructions).
// zx for the next step is software-prefetched.
// =====================================================================
#define WRW 68
#define SMEM_B (G4*WRW*4 + 2*G4*4 + 2*Uu*4)   // 139264 + 4096 + 1024 = 144384

__global__ void __launch_bounds__(512, 1)
lstm_rec(const float* __restrict__ Wr_f, const float* __restrict__ Wr_b)
{
    extern __shared__ char smem[];
    unsigned* wr = (unsigned*)smem;                 // [j*68 + kw] = bf16x2(Wr[2kw][j], Wr[2kw+1][j])
    float* z_s = (float*)(smem + G4 * WRW * 4);     // [2][512]
    float* h_s = z_s + 2 * G4;                      // [2][128]

    const int tid  = threadIdx.x;
    const int bx   = blockIdx.x;
    const int dir  = bx >> 6;
    const int pair = bx & 63;
    const int b0   = 2 * pair;
    const float* Wr = dir ? Wr_b : Wr_f;

    // stage weights
    for (int idx = tid; idx < G4 * 64; idx += 512) {
        int j = idx & 511, kw = idx >> 9;
        __nv_bfloat162 p = __floats2bfloat162_rn(Wr[(2 * kw) * G4 + j],
                                                 Wr[(2 * kw + 1) * G4 + j]);
        wr[j * WRW + kw] = reinterpret_cast<unsigned&>(p);
    }
    if (tid < 256) h_s[tid] = 0.f;
    float c_reg = 0.f;
    __syncthreads();

    const int j = tid;
    const uint4* wp = (const uint4*)(wr + j * WRW);
    const float* zx0 = g_zx + ((size_t)dir * BT + (size_t)(b0 + 0) * Tt) * G4;
    const float* zx1 = g_zx + ((size_t)dir * BT + (size_t)(b0 + 1) * Tt) * G4;
    float* hout = g_h + (size_t)dir * BT * Uu;

    int t0 = dir ? (Tt - 1) : 0;
    float pz0 = zx0[(size_t)t0 * G4 + j];
    float pz1 = zx1[(size_t)t0 * G4 + j];

    for (int step = 0; step < Tt; step++) {
        const int t = dir ? (Tt - 1 - step) : step;
        float cz0 = pz0, cz1 = pz1;
        int tn = dir ? (t - 1) : (t + 1);
        tn = min(max(tn, 0), Tt - 1);
        pz0 = zx0[(size_t)tn * G4 + j];          // prefetch next step
        pz1 = zx1[(size_t)tn * G4 + j];

        ull a00 = 0, a01 = 0, a10 = 0, a11 = 0;
#pragma unroll
        for (int kk = 0; kk < 16; kk++) {
            uint4 wv = wp[kk];                    // 8 bf16 weights (k = 8kk..8kk+7)
            ull w01 = bfpair(wv.x), w23 = bfpair(wv.y);
            ull w45 = bfpair(wv.z), w67 = bfpair(wv.w);
            ull hA, hB, hC, hD;
            ldsv2(hA, hB, h_s + 8 * kk);          // batch0 h[8kk..+3]
            ldsv2(hC, hD, h_s + 8 * kk + 4);      // batch0 h[8kk+4..+7]
            a00 = fma2(w01, hA, a00);
            a01 = fma2(w23, hB, a01);
            a00 = fma2(w45, hC, a00);
            a01 = fma2(w67, hD, a01);
            ldsv2(hA, hB, h_s + Uu + 8 * kk);     // batch1
            ldsv2(hC, hD, h_s + Uu + 8 * kk + 4);
            a10 = fma2(w01, hA, a10);
            a11 = fma2(w23, hB, a11);
            a10 = fma2(w45, hC, a10);
            a11 = fma2(w67, hD, a11);
        }
        float x0, x1, y0, y1;
        unpk2(a00, x0, x1); unpk2(a01, y0, y1);
        z_s[j] = ((x0 + x1) + (y0 + y1)) + cz0;
        unpk2(a10, x0, x1); unpk2(a11, y0, y1);
        z_s[G4 + j] = ((x0 + x1) + (y0 + y1)) + cz1;
        __syncthreads();

        if (tid < 256) {
            int bsel = tid >> 7, jj = tid & 127;
            const float* z = z_s + bsel * G4;
            float zi = z[jj], zf = z[jj + 128], zg = z[jj + 256], zo = z[jj + 384];
            c_reg = sigfast(zf) * c_reg + sigfast(zi) * tanhfast(zg);
            float h = sigfast(zo) * tanhfast(c_reg);
            h_s[bsel * Uu + jj] = h;
            hout[((size_t)(b0 + bsel) * Tt + t) * Uu + jj] = h;
        }
        __syncthreads();
    }
}

// =====================================================================
// Kernel C: em = [h_f, h_b] @ crf_kernel + bias.  grid BT/8, block 256.
// ck transposed to [k][u] with pad 260 (== 4 mod 32 -> conflict-free);
// both fma2 operands pair naturally over u.
// =====================================================================
#define CKP 260
__global__ void em_gemm(const float* __restrict__ ck, const float* __restrict__ cb)
{
    __shared__ float ck_t[Kk][CKP];         // [k][u]
    __shared__ float hs[8][2 * Uu];         // 8 rows x 256
    __shared__ float cb_s[Kk];

    const int tid = threadIdx.x;
    const int bt0 = blockIdx.x * 8;

    for (int idx = tid; idx < 2 * Uu * Kk; idx += 256) {
        int u = idx >> 5, k = idx & 31;
        ck_t[k][u] = ck[idx];
    }
    if (tid < Kk) cb_s[tid] = cb[tid];
    for (int idx = tid; idx < 8 * 2 * Uu; idx += 256) {
        int r = idx >> 8, u = idx & 255;
        hs[r][u] = (u < Uu) ? g_h[(size_t)(bt0 + r) * Uu + u]
                            : g_h[(size_t)BT * Uu + (size_t)(bt0 + r) * Uu + (u - Uu)];
    }
    __syncthreads();

    const int r = tid >> 5, k = tid & 31;
    ull acc0 = 0, acc1 = 0;
#pragma unroll 8
    for (int u = 0; u < 2 * Uu; u += 4) {
        ull h01, h23, c01, c23;
        ldsv2(h01, h23, &hs[r][u]);
        ldsv2(c01, c23, &ck_t[k][u]);
        acc0 = fma2(h01, c01, acc0);
        acc1 = fma2(h23, c23, acc1);
    }
    float x0, x1, y0, y1;
    unpk2(acc0, x0, x1); unpk2(acc1, y0, y1);
    g_em[(size_t)(bt0 + r) * Kk + k] = ((x0 + x1) + (y0 + y1)) + cb_s[k];
}

// =====================================================================
// Kernel D: CRF logZ. 128 blocks x 32 threads (one warp per batch).
// - reference m = lane-0 alpha broadcast (1 shfl instead of 5-deep max;
//   lane spread is bounded by |em|+|trans| spread << 80, so exp is safe)
// - 4-deep register prefetch ring for em
// - 4-way split accumulators for the 32-term matvec
// =====================================================================
__global__ void crf_logz(const float* __restrict__ trans, float* __restrict__ out)
{
    const float L2E = 1.4426950408889634f, LN2 = 0.6931471805599453f;
    const int b = blockIdx.x;
    const int k = threadIdx.x;
    const unsigned full = 0xffffffffu;

    float Ecol[Kk];
#pragma unroll
    for (int jj = 0; jj < Kk; jj++)
        Ecol[jj] = ex2f(trans[jj * Kk + k] * L2E);

    const float* em = g_em + (size_t)b * Tt * Kk;
    float alpha = em[k];                 // t = 0
    float f0 = em[1 * Kk + k];
    float f1 = em[2 * Kk + k];
    float f2 = em[3 * Kk + k];
    float f3 = em[4 * Kk + k];

#pragma unroll 4
    for (int t = 1; t < Tt; t++) {
        float emt = f0; f0 = f1; f1 = f2; f2 = f3;
        int tp = t + 4;
        f3 = (tp < Tt) ? em[(size_t)tp * Kk + k] : 0.f;

        float m = __shfl_sync(full, alpha, 0);
        float e = ex2f((alpha - m) * L2E);
        float s0 = 0.f, s1 = 0.f, s2 = 0.f, s3 = 0.f;
#pragma unroll
        for (int jj = 0; jj < Kk; jj += 4) {
            s0 += __shfl_sync(full, e, jj    ) * Ecol[jj    ];
            s1 += __shfl_sync(full, e, jj + 1) * Ecol[jj + 1];
            s2 += __shfl_sync(full, e, jj + 2) * Ecol[jj + 2];
            s3 += __shfl_sync(full, e, jj + 3) * Ecol[jj + 3];
        }
        alpha = lg2f((s0 + s1) + (s2 + s3)) * LN2 + m + emt;
    }

    float m = alpha;
#pragma unroll
    for (int o = 16; o; o >>= 1) m = fmaxf(m, __shfl_xor_sync(full, m, o));
    float s = ex2f((alpha - m) * L2E);
#pragma unroll
    for (int o = 16; o; o >>= 1) s += __shfl_xor_sync(full, s, o);
    if (k == 0) out[b] = m + lg2f(s) * LN2;
}

// =====================================================================
extern "C" void kernel_launch(void* const* d_in, const int* in_sizes, int n_in,
                              void* d_out, int out_size)
{
    const int*   tokens = (const int*)  d_in[0];
    const float* emb    = (const float*)d_in[1];
    const float* Wk_f   = (const float*)d_in[2];
    const float* Wr_f   = (const float*)d_in[3];
    const float* b_f    = (const float*)d_in[4];
    const float* Wk_b   = (const float*)d_in[5];
    const float* Wr_b   = (const float*)d_in[6];
    const float* b_b    = (const float*)d_in[7];
    const float* ck     = (const float*)d_in[8];
    const float* cb     = (const float*)d_in[9];
    const float* trans  = (const float*)d_in[10];
    float* out = (float*)d_out;

    cudaFuncSetAttribute(lstm_rec, cudaFuncAttributeMaxDynamicSharedMemorySize, SMEM_B);

    input_gemm<<<dim3(BT / 64, 16), 256>>>(tokens, emb, Wk_f, b_f, Wk_b, b_b);
    lstm_rec<<<128, 512, SMEM_B>>>(Wr_f, Wr_b);
    em_gemm<<<BT / 8, 256>>>(ck, cb);
    crf_logz<<<Bb, 32>>>(trans, out);
}

// round 3
// speedup vs baseline: 1.2242x; 1.0291x over previous
#include <cuda_runtime.h>
#include <cuda_bf16.h>
#include <cstdint>

typedef unsigned long long ull;

#define Bb   128
#define Tt   512
#define Ee   100
#define Uu   128
#define Kk   32
#define G4   512          // 4*U
#define BT   (Bb*Tt)      // 65536

// ---------------- scratch (static device allocations) ----------------
__device__ float g_zx[(size_t)2 * BT * G4];   // [dir][b*T+t][512]
__device__ float g_h [(size_t)2 * BT * Uu];   // [dir][b*T+t][128]
__device__ float g_em[(size_t)BT * Kk];       // [b*T+t][32]

// ---------------- fast math helpers ----------------
__device__ __forceinline__ float ex2f(float x){ float r; asm("ex2.approx.f32 %0, %1;" : "=f"(r) : "f"(x)); return r; }
__device__ __forceinline__ float lg2f(float x){ float r; asm("lg2.approx.f32 %0, %1;" : "=f"(r) : "f"(x)); return r; }
__device__ __forceinline__ float tanhfast(float x){ float r; asm("tanh.approx.f32 %0, %1;" : "=f"(r) : "f"(x)); return r; }
__device__ __forceinline__ float sigfast(float x){ return 0.5f * tanhfast(0.5f * x) + 0.5f; }
__device__ __forceinline__ float rcpf(float x){ float r; asm("rcp.approx.f32 %0, %1;" : "=f"(r) : "f"(x)); return r; }

// ---------------- f32x2 (FFMA2) helpers ----------------
__device__ __forceinline__ ull bfpair(unsigned u){
    unsigned lo = u << 16;
    unsigned hi = u & 0xffff0000u;
    ull r; asm("mov.b64 %0, {%1, %2};" : "=l"(r) : "r"(lo), "r"(hi)); return r;
}
__device__ __forceinline__ ull dup2(float x){
    ull r; asm("mov.b64 %0, {%1, %1};" : "=l"(r) : "f"(x)); return r;
}
__device__ __forceinline__ ull fma2(ull a, ull b, ull c){
    ull d; asm("fma.rn.f32x2 %0, %1, %2, %3;" : "=l"(d) : "l"(a), "l"(b), "l"(c)); return d;
}
__device__ __forceinline__ void unpk2(ull v, float& lo, float& hi){
    asm("mov.b64 {%0, %1}, %2;" : "=f"(lo), "=f"(hi) : "l"(v));
}
__device__ __forceinline__ void ldsv2(ull& a, ull& b, const void* p){
    unsigned s = (unsigned)__cvta_generic_to_shared(p);
    asm volatile("ld.shared.v2.u64 {%0, %1}, [%2];" : "=l"(a), "=l"(b) : "r"(s));
}

// =====================================================================
// Kernel A: zx[dir][bt][j] = emb[tokens[bt]] @ Wk_dir + b_dir
// grid (512, 8), block 256. Tile 128x128, 8x8 per thread, FMA-pipe bound.
// =====================================================================
#define XST 132
#define SMEM_A ((Ee*XST + Ee*128)*4 + 128*4 + 128*4)   // 105024

__global__ void __launch_bounds__(256, 2)
input_gemm(const int* __restrict__ tokens, const float* __restrict__ emb,
           const float* __restrict__ Wk_f, const float* __restrict__ b_f,
           const float* __restrict__ Wk_b, const float* __restrict__ b_b)
{
    extern __shared__ char sm[];
    float* xs_t = (float*)sm;                  // [100][132]  x transposed
    float* ws   = xs_t + Ee * XST;             // [100][128]
    int*   tok  = (int*)(ws + Ee * 128);       // [128]
    float* bs   = (float*)(tok + 128);         // [128]

    const int tid = threadIdx.x;
    const int r0  = blockIdx.x * 128;
    const int c0  = blockIdx.y * 128;          // 0..1023
    const int dir = c0 >> 9;
    const int cl  = c0 & 511;
    const float* Wk = dir ? Wk_b : Wk_f;
    const float* bv = dir ? b_b  : b_f;

    if (tid < 128) { tok[tid] = tokens[r0 + tid]; bs[tid] = bv[cl + tid]; }
    __syncthreads();

    for (int idx = tid; idx < 128 * Ee; idx += 256) {
        int r = idx / Ee, k = idx - r * Ee;            // consecutive tid -> consecutive k (coalesced emb)
        xs_t[k * XST + r] = emb[(size_t)tok[r] * Ee + k];
    }
    for (int idx = tid; idx < Ee * 128; idx += 256) {
        int k = idx >> 7, c = idx & 127;
        ws[k * 128 + c] = Wk[k * G4 + cl + c];
    }
    __syncthreads();

    const int ty = tid >> 4, tx = tid & 15;
    const float* xrow = xs_t + 8 * ty;
    const float* wrow = ws + 8 * tx;

    ull acc[8][4];
#pragma unroll
    for (int i = 0; i < 8; i++)
#pragma unroll
        for (int j = 0; j < 4; j++) acc[i][j] = 0ull;

#pragma unroll 2
    for (int k = 0; k < Ee; k++) {
        ull w01, w23, w45, w67;
        ldsv2(w01, w23, wrow + k * 128);
        ldsv2(w45, w67, wrow + k * 128 + 4);
        float4 xa = *(const float4*)(xrow + k * XST);
        float4 xb = *(const float4*)(xrow + k * XST + 4);
        float xr[8] = {xa.x, xa.y, xa.z, xa.w, xb.x, xb.y, xb.z, xb.w};
#pragma unroll
        for (int i = 0; i < 8; i++) {
            ull xd = dup2(xr[i]);
            acc[i][0] = fma2(xd, w01, acc[i][0]);
            acc[i][1] = fma2(xd, w23, acc[i][1]);
            acc[i][2] = fma2(xd, w45, acc[i][2]);
            acc[i][3] = fma2(xd, w67, acc[i][3]);
        }
    }

#pragma unroll
    for (int i = 0; i < 8; i++) {
        int rg = r0 + 8 * ty + i;
        float v[8];
        unpk2(acc[i][0], v[0], v[1]);
        unpk2(acc[i][1], v[2], v[3]);
        unpk2(acc[i][2], v[4], v[5]);
        unpk2(acc[i][3], v[6], v[7]);
        float* dst = g_zx + ((size_t)dir * BT + rg) * G4 + cl + 8 * tx;
#pragma unroll
        for (int j = 0; j < 8; j++) dst[j] = v[j] + bs[8 * tx + j];
    }
}

// =====================================================================
// Kernel B: LSTM recurrence, quad-split. 128 blocks x 512 threads.
// Thread t: unit u = t>>2, k-quarter q = t&3; computes all-4-gate partials
// for both batches over k in [32q,32q+32). Quad shfl reduction; gates in
// lanes q<2 (batch=q). ONE __syncthreads per step.
// =====================================================================
#define WSTRIDE 68
#define HPADB   160                 // per-batch h stride (8-word pad per 32 units)
#define SMEM_B  (512*WSTRIDE*4 + 2*HPADB*4)   // 139264 + 1280 = 140544

__device__ __forceinline__ int hidx(int u){ return (u >> 5) * 40 + (u & 31); }

__global__ void __launch_bounds__(512, 1)
lstm_rec(const float* __restrict__ Wr_f, const float* __restrict__ Wr_b)
{
    extern __shared__ char smem[];
    unsigned* w_s = (unsigned*)smem;                    // [512][68]
    float* h_s = (float*)(smem + 512 * WSTRIDE * 4);    // [2][160]

    const int tid = threadIdx.x;
    const int u = tid >> 2, q = tid & 3;
    const int bx  = blockIdx.x;
    const int dir = bx >> 6;
    const int b0  = 2 * (bx & 63);
    const float* Wr = dir ? Wr_b : Wr_f;

    // stage weights: w_s[tid][g*16+kk] = bf16x2(Wr[32q+2kk][u+128g], Wr[32q+2kk+1][u+128g])
    {
        unsigned* wp = w_s + tid * WSTRIDE;
#pragma unroll
        for (int g = 0; g < 4; g++) {
            int c = u + 128 * g;
            for (int kk = 0; kk < 16; kk++) {
                int k = 32 * q + 2 * kk;
                __nv_bfloat162 pr = __floats2bfloat162_rn(Wr[k * G4 + c], Wr[(k + 1) * G4 + c]);
                wp[g * 16 + kk] = reinterpret_cast<unsigned&>(pr);
            }
        }
    }
    if (tid < 2 * HPADB) h_s[tid] = 0.f;
    __syncthreads();

    const uint4* wq = (const uint4*)(w_s + tid * WSTRIDE);   // 16 uint4
    const bool fin = (q < 2);
    const int bb = b0 + (q & 1);
    const float* zxp = g_zx + ((size_t)dir * BT + (size_t)bb * Tt) * G4;
    float* hout = g_h + ((size_t)dir * BT + (size_t)bb * Tt) * Uu;
    const float* hb0 = h_s + 40 * q;
    const float* hb1 = h_s + HPADB + 40 * q;
    const unsigned full = 0xffffffffu;

    float c_reg = 0.f;
    int t0 = dir ? (Tt - 1) : 0;
    float pz0 = 0.f, pz1 = 0.f, pz2 = 0.f, pz3 = 0.f;
    if (fin) {
        const float* zr = zxp + (size_t)t0 * G4;
        pz0 = zr[u]; pz1 = zr[u + 128]; pz2 = zr[u + 256]; pz3 = zr[u + 384];
    }

    for (int step = 0; step < Tt; step++) {
        const int t = dir ? (Tt - 1 - step) : step;
        float cz0 = pz0, cz1 = pz1, cz2 = pz2, cz3 = pz3;
        int tn = dir ? (t - 1) : (t + 1);
        tn = min(max(tn, 0), Tt - 1);
        if (fin) {
            const float* zr = zxp + (size_t)tn * G4;
            pz0 = zr[u]; pz1 = zr[u + 128]; pz2 = zr[u + 256]; pz3 = zr[u + 384];
        }

        ull a0[4] = {0,0,0,0}, a1[4] = {0,0,0,0};
#pragma unroll
        for (int p = 0; p < 4; p++) {
            ull h0a, h0b, h0c, h0d, h1a, h1b, h1c, h1d;
            ldsv2(h0a, h0b, hb0 + 8 * p);
            ldsv2(h0c, h0d, hb0 + 8 * p + 4);
            ldsv2(h1a, h1b, hb1 + 8 * p);
            ldsv2(h1c, h1d, hb1 + 8 * p + 4);
#pragma unroll
            for (int g = 0; g < 4; g++) {
                uint4 wv = wq[g * 4 + p];
                ull w01 = bfpair(wv.x), w23 = bfpair(wv.y);
                ull w45 = bfpair(wv.z), w67 = bfpair(wv.w);
                a0[g] = fma2(w01, h0a, a0[g]);
                a0[g] = fma2(w23, h0b, a0[g]);
                a0[g] = fma2(w45, h0c, a0[g]);
                a0[g] = fma2(w67, h0d, a0[g]);
                a1[g] = fma2(w01, h1a, a1[g]);
                a1[g] = fma2(w23, h1b, a1[g]);
                a1[g] = fma2(w45, h1c, a1[g]);
                a1[g] = fma2(w67, h1d, a1[g]);
            }
        }
        // collapse f32x2 -> f32, butterfly over the quad (lanes xor 1, 2)
        float d0[4], d1[4];
#pragma unroll
        for (int g = 0; g < 4; g++) {
            float lo, hi;
            unpk2(a0[g], lo, hi); d0[g] = lo + hi;
            unpk2(a1[g], lo, hi); d1[g] = lo + hi;
        }
#pragma unroll
        for (int o = 1; o <= 2; o <<= 1) {
#pragma unroll
            for (int g = 0; g < 4; g++) {
                d0[g] += __shfl_xor_sync(full, d0[g], o);
                d1[g] += __shfl_xor_sync(full, d1[g], o);
            }
        }

        if (fin) {
            float zi = ((q == 0) ? d0[0] : d1[0]) + cz0;
            float zf = ((q == 0) ? d0[1] : d1[1]) + cz1;
            float zg = ((q == 0) ? d0[2] : d1[2]) + cz2;
            float zo = ((q == 0) ? d0[3] : d1[3]) + cz3;
            c_reg = sigfast(zf) * c_reg + sigfast(zi) * tanhfast(zg);
            float h = sigfast(zo) * tanhfast(c_reg);
            h_s[q * HPADB + hidx(u)] = h;
            hout[(size_t)t * Uu + u] = h;
        }
        __syncthreads();
    }
}

// =====================================================================
// Kernel C: em = [h_f, h_b] @ crf_kernel + bias.  grid BT/8, block 256.
// =====================================================================
#define CKP 260
__global__ void em_gemm(const float* __restrict__ ck, const float* __restrict__ cb)
{
    __shared__ float ck_t[Kk][CKP];
    __shared__ float hs[8][2 * Uu];
    __shared__ float cb_s[Kk];

    const int tid = threadIdx.x;
    const int bt0 = blockIdx.x * 8;

    for (int idx = tid; idx < 2 * Uu * Kk; idx += 256) {
        int uu = idx >> 5, k = idx & 31;
        ck_t[k][uu] = ck[idx];
    }
    if (tid < Kk) cb_s[tid] = cb[tid];
    for (int idx = tid; idx < 8 * 2 * Uu; idx += 256) {
        int r = idx >> 8, uu = idx & 255;
        hs[r][uu] = (uu < Uu) ? g_h[(size_t)(bt0 + r) * Uu + uu]
                              : g_h[(size_t)BT * Uu + (size_t)(bt0 + r) * Uu + (uu - Uu)];
    }
    __syncthreads();

    const int r = tid >> 5, k = tid & 31;
    ull acc0 = 0, acc1 = 0;
#pragma unroll 8
    for (int uu = 0; uu < 2 * Uu; uu += 4) {
        ull h01, h23, c01, c23;
        ldsv2(h01, h23, &hs[r][uu]);
        ldsv2(c01, c23, &ck_t[k][uu]);
        acc0 = fma2(h01, c01, acc0);
        acc1 = fma2(h23, c23, acc1);
    }
    float x0, x1, y0, y1;
    unpk2(acc0, x0, x1); unpk2(acc1, y0, y1);
    g_em[(size_t)(bt0 + r) * Kk + k] = ((x0 + x1) + (y0 + y1)) + cb_s[k];
}

// =====================================================================
// Kernel D: CRF logZ, linear-space recurrence (no exp/log on the chain).
// v_t = p / p0,  p = (sum_j v_j * E[j][k]) * exp(em_t[k]),  Ml += lg2(p0).
// exp(em) precomputed in an 8-deep ring; dot via double-buffered smem.
// =====================================================================
__global__ void crf_logz(const float* __restrict__ trans, float* __restrict__ out)
{
    const float L2E = 1.4426950408889634f, LN2 = 0.6931471805599453f;
    __shared__ float vsb[2][32];
    const int b = blockIdx.x;
    const int k = threadIdx.x;
    const unsigned full = 0xffffffffu;

    float Ecol[Kk];
#pragma unroll
    for (int jj = 0; jj < Kk; jj++)
        Ecol[jj] = ex2f(trans[jj * Kk + k] * L2E);

    const float* em = g_em + (size_t)b * Tt * Kk;

    float uring[8];
#pragma unroll
    for (int i = 0; i < 8; i++)
        uring[i] = ex2f(em[(size_t)(1 + i) * Kk + k] * L2E);

    float e0 = em[k];
    float m0 = __shfl_sync(full, e0, 0);
    float v  = ex2f((e0 - m0) * L2E);
    float Ml = m0 * L2E;                 // accumulated log2 offset

    for (int t = 1; t < Tt; t++) {
        float* vs = vsb[t & 1];
        vs[k] = v;
        __syncwarp();
        float s0 = 0.f, s1 = 0.f, s2 = 0.f, s3 = 0.f;
#pragma unroll
        for (int j = 0; j < Kk; j += 4) {
            float4 vv = *(const float4*)(vs + j);
            s0 += vv.x * Ecol[j    ];
            s1 += vv.y * Ecol[j + 1];
            s2 += vv.z * Ecol[j + 2];
            s3 += vv.w * Ecol[j + 3];
        }
        float p = ((s0 + s1) + (s2 + s3)) * uring[(t - 1) & 7];
        int tp = t + 8;
        uring[(t - 1) & 7] = (tp < Tt) ? ex2f(em[(size_t)tp * Kk + k] * L2E) : 1.0f;
        float p0 = __shfl_sync(full, p, 0);
        v = p * rcpf(p0);
        Ml += lg2f(p0);
    }

    float sv = v;
#pragma unroll
    for (int o = 16; o; o >>= 1) sv += __shfl_xor_sync(full, sv, o);
    if (k == 0) out[b] = (Ml + lg2f(sv)) * LN2;
}

// =====================================================================
extern "C" void kernel_launch(void* const* d_in, const int* in_sizes, int n_in,
                              void* d_out, int out_size)
{
    const int*   tokens = (const int*)  d_in[0];
    const float* emb    = (const float*)d_in[1];
    const float* Wk_f   = (const float*)d_in[2];
    const float* Wr_f   = (const float*)d_in[3];
    const float* b_f    = (const float*)d_in[4];
    const float* Wk_b   = (const float*)d_in[5];
    const float* Wr_b   = (const float*)d_in[6];
    const float* b_b    = (const float*)d_in[7];
    const float* ck     = (const float*)d_in[8];
    const float* cb     = (const float*)d_in[9];
    const float* trans  = (const float*)d_in[10];
    float* out = (float*)d_out;

    cudaFuncSetAttribute(input_gemm, cudaFuncAttributeMaxDynamicSharedMemorySize, SMEM_A);
    cudaFuncSetAttribute(lstm_rec,   cudaFuncAttributeMaxDynamicSharedMemorySize, SMEM_B);

    input_gemm<<<dim3(BT / 128, 8), 256, SMEM_A>>>(tokens, emb, Wk_f, b_f, Wk_b, b_b);
    lstm_rec<<<128, 512, SMEM_B>>>(Wr_f, Wr_b);
    em_gemm<<<BT / 8, 256>>>(ck, cb);
    crf_logz<<<Bb, 32>>>(trans, out);
}